// round 13
// baseline (speedup 1.0000x reference)
#include <cuda_runtime.h>
#include <cstdint>

#define B_TOTAL 16384
#define RS 72                // rel row stride (floats); phase-conflict-free LDS.64
#define RELTILE (16 * RS)    // 1152 floats per m-tile buffer
#define NCTA 444             // 148 SMs x (>=3) resident CTAs
#define BSTRIDE (NCTA * 8)   // warp-batch stride = 3552

// ---- dynamic smem layout (float offsets), ~46.3 KB total ----
#define OFF_WPB  0           // uint2[1024]: bf16-packed B-frags of W1_lower (8 KB)
#define OFF_W2   2048        // float[64]
#define OFF_UEP  2112        // float[8][64]: per-warp uep[j]
#define OFF_REL  2624        // float[8][RELTILE]: per-warp rel buffer (36 KB)
#define SMEM_FLOATS (OFF_REL + 8 * RELTILE)
#define SMEM_BYTES  (SMEM_FLOATS * 4)

__device__ __forceinline__ void cp16(float* s, const float* g) {
    uint32_t sa = (uint32_t)__cvta_generic_to_shared(s);
    asm volatile("cp.async.cg.shared.global [%0], [%1], 16;\n" :: "r"(sa), "l"(g));
}
template <int N>
__device__ __forceinline__ void cp_wait() { asm volatile("cp.async.wait_group %0;\n" :: "n"(N)); }

// pack two f32 -> bf16x2 (lo = first arg)
__device__ __forceinline__ uint32_t pack_bf16(float lo, float hi) {
    uint32_t r;
    asm("cvt.rn.bf16x2.f32 %0, %1, %2;" : "=r"(r) : "f"(hi), "f"(lo));
    return r;
}

__device__ __forceinline__ float4 ldg_stream4(const float* g) {
    float4 v;
    asm volatile("ld.global.nc.L1::no_allocate.v4.f32 {%0,%1,%2,%3}, [%4];\n"
                 : "=f"(v.x), "=f"(v.y), "=f"(v.z), "=f"(v.w) : "l"(g));
    return v;
}
__device__ __forceinline__ void stg_stream4(float* g, float4 v) {
    asm volatile("st.global.cs.v4.f32 [%0], {%1,%2,%3,%4};\n"
                 :: "l"(g), "f"(v.x), "f"(v.y), "f"(v.z), "f"(v.w) : "memory");
}

// stage one 16x64 rel m-tile -> buf (row stride RS), per-warp, coalesced 16B chunks
__device__ __forceinline__ void stage_tile(float* buf, const float* __restrict__ src, int lane) {
#pragma unroll
    for (int c = 0; c < 8; c++) {
        int i = lane + c * 32;          // chunk 0..255
        int r = i >> 4, s4 = i & 15;
        cp16(buf + r * RS + s4 * 4, src + r * 64 + s4 * 4);
    }
    asm volatile("cp.async.commit_group;\n");
}

__global__ __launch_bounds__(256, 4) void agg_kernel(
    const float* __restrict__ self_v,
    const float* __restrict__ nv,
    const float* __restrict__ rel,
    const float* __restrict__ ue,
    const float* __restrict__ W1,
    const float* __restrict__ b1,
    const float* __restrict__ w2,
    const float* __restrict__ b2,
    float* __restrict__ out)
{
    extern __shared__ __align__(16) float smem[];
    uint2* sWpB = reinterpret_cast<uint2*>(smem + OFF_WPB);
    float* sW2  = smem + OFF_W2;

    const int tid  = threadIdx.x;
    const int warp = tid >> 5;
    const int lane = tid & 31;
    const int g = lane >> 2;          // groupID
    const int q = lane & 3;           // threadID_in_group

    float* myU = smem + OFF_UEP + warp * 64;   // uep[j]
    float* buf = smem + OFF_REL + warp * RELTILE;

    // ---- one-time W staging: bf16 B-frags for m16n8k16 (once per persistent CTA) ----
    // sWpB[(jt*4+kst)*32 + lane] = { pack(W[k0+2q][j], W[k0+2q+1][j]),
    //                               pack(W[k0+2q+8][j], W[k0+2q+9][j]) },  k0 = 16*kst, j = 8*jt+g
    for (int i = tid; i < 1024; i += 256) {
        int l2 = i & 31, jtk = i >> 5;
        int gg = l2 >> 2, qq = l2 & 3;
        int jt = jtk >> 2, kst = jtk & 3;
        int col = 8 * jt + gg;
        int row = 64 + 16 * kst + 2 * qq;
        float x0 = __ldg(W1 + (row)     * 64 + col);
        float x1 = __ldg(W1 + (row + 1) * 64 + col);
        float x2 = __ldg(W1 + (row + 8) * 64 + col);
        float x3 = __ldg(W1 + (row + 9) * 64 + col);
        sWpB[i] = make_uint2(pack_bf16(x0, x1), pack_bf16(x2, x3));
    }
    if (tid < 64) sW2[tid] = __ldg(w2 + tid);
    __syncthreads();

    const float b2v = __ldg(b2);
    const int c4 = lane & 15, half = lane >> 4;

    int b = blockIdx.x * 8 + warp;
    if (b < B_TOTAL) {
        // prologue: prefetch first batch's m-tile 0
        stage_tile(buf, rel + (size_t)b * 4096, lane);

        for (;;) {
            const float* relb = rel + (size_t)b * 4096;
            const float* nvb  = nv  + (size_t)b * 4096;
            const int nb = b + BSTRIDE;
            const bool has_next = nb < B_TOTAL;

            // ---- uep[j] = b1[j] + ue[b] @ W1_upper[:,j] (fp32; overlaps cp.async) ----
            {
                const float* ub = ue + (size_t)b * 64;
                float uev0 = __ldg(ub + lane);
                float uev1 = __ldg(ub + lane + 32);
                float acc0 = __ldg(b1 + lane);
                float acc1 = __ldg(b1 + lane + 32);
#pragma unroll
                for (int k = 0; k < 64; k++) {
                    float uk = __shfl_sync(0xffffffffu, (k < 32) ? uev0 : uev1, k & 31);
                    acc0 = fmaf(uk, __ldg(W1 + k * 64 + lane),      acc0);
                    acc1 = fmaf(uk, __ldg(W1 + k * 64 + lane + 32), acc1);
                }
                myU[lane]      = acc0;
                myU[lane + 32] = acc1;
            }

            float4 agg = make_float4(0.f, 0.f, 0.f, 0.f);
            float teAcc = 0.f;

            // ---- 4 m-tiles of 16 neighbors; bf16 MMA + fused aggregation ----
#pragma unroll
            for (int mt = 0; mt < 4; mt++) {
                cp_wait<0>();
                __syncwarp();

                // A-frags: LDS.64 fp32 pairs -> bf16x2 (phase-conflict-free, RS=72)
                uint32_t a[4][4];
#pragma unroll
                for (int kst = 0; kst < 4; kst++) {
                    const float* r0 = buf + g * RS + 16 * kst;
                    const float* r1 = r0 + 8 * RS;
                    float2 p0 = *reinterpret_cast<const float2*>(r0 + 2 * q);
                    float2 p1 = *reinterpret_cast<const float2*>(r1 + 2 * q);
                    float2 p2 = *reinterpret_cast<const float2*>(r0 + 2 * q + 8);
                    float2 p3 = *reinterpret_cast<const float2*>(r1 + 2 * q + 8);
                    a[kst][0] = pack_bf16(p0.x, p0.y);
                    a[kst][1] = pack_bf16(p1.x, p1.y);
                    a[kst][2] = pack_bf16(p2.x, p2.y);
                    a[kst][3] = pack_bf16(p3.x, p3.y);
                }

                // restage: next tile, or next batch's tile 0 (pipeline never drains)
                if (mt < 3)           stage_tile(buf, relb + (mt + 1) * 1024, lane);
                else if (has_next)    stage_tile(buf, rel + (size_t)nb * 4096, lane);

                float s0 = 0.f, s1 = 0.f;   // scores for neighbors mt*16+g, +8
#pragma unroll
                for (int jt = 0; jt < 8; jt++) {
                    float c0 = 0.f, c1 = 0.f, c2 = 0.f, c3 = 0.f;
#pragma unroll
                    for (int kst = 0; kst < 4; kst++) {
                        uint2 bv = sWpB[(jt * 4 + kst) * 32 + lane];
                        asm volatile(
                            "mma.sync.aligned.m16n8k16.row.col.f32.bf16.bf16.f32 "
                            "{%0,%1,%2,%3}, {%4,%5,%6,%7}, {%8,%9}, {%0,%1,%2,%3};\n"
                            : "+f"(c0), "+f"(c1), "+f"(c2), "+f"(c3)
                            : "r"(a[kst][0]), "r"(a[kst][1]), "r"(a[kst][2]), "r"(a[kst][3]),
                              "r"(bv.x), "r"(bv.y));
                    }
                    float u0 = myU[8 * jt + 2 * q], u1 = myU[8 * jt + 2 * q + 1];
                    float v0 = sW2[8 * jt + 2 * q], v1 = sW2[8 * jt + 2 * q + 1];
                    s0 += fmaxf(c0 + u0, 0.f) * v0 + fmaxf(c1 + u1, 0.f) * v1;
                    s1 += fmaxf(c2 + u0, 0.f) * v0 + fmaxf(c3 + u1, 0.f) * v1;
                }
                s0 += __shfl_xor_sync(0xffffffffu, s0, 1);
                s0 += __shfl_xor_sync(0xffffffffu, s0, 2);
                s1 += __shfl_xor_sync(0xffffffffu, s1, 1);
                s1 += __shfl_xor_sync(0xffffffffu, s1, 2);

                float e0 = __expf(1.f / (1.f + __expf(-(s0 + b2v))));
                float e1 = __expf(1.f / (1.f + __expf(-(s1 + b2v))));
                teAcc += e0 + e1;

                // fused aggregation for this tile's 16 neighbors (streaming loads)
                const float* nvt = nvb + mt * 1024;
#pragma unroll
                for (int i = 0; i < 8; i++) {
                    int r = 2 * i + half;                    // 0..15
                    float er = (i < 4)
                        ? __shfl_sync(0xffffffffu, e0, 4 * r)
                        : __shfl_sync(0xffffffffu, e1, 4 * (r - 8));
                    float4 v = ldg_stream4(nvt + r * 64 + c4 * 4);
                    agg.x = fmaf(er, v.x, agg.x);
                    agg.y = fmaf(er, v.y, agg.y);
                    agg.z = fmaf(er, v.z, agg.z);
                    agg.w = fmaf(er, v.w, agg.w);
                }
            }

            // softmax denominator (teAcc identical across q-lanes; sum over g)
            teAcc += __shfl_xor_sync(0xffffffffu, teAcc, 4);
            teAcc += __shfl_xor_sync(0xffffffffu, teAcc, 8);
            teAcc += __shfl_xor_sync(0xffffffffu, teAcc, 16);
            float inv_te = __fdividef(1.f, teAcc);

            agg.x += __shfl_xor_sync(0xffffffffu, agg.x, 16);
            agg.y += __shfl_xor_sync(0xffffffffu, agg.y, 16);
            agg.z += __shfl_xor_sync(0xffffffffu, agg.z, 16);
            agg.w += __shfl_xor_sync(0xffffffffu, agg.w, 16);

            if (lane < 16) {
                stg_stream4(out + (size_t)b * 128 + 64 + c4 * 4,
                            make_float4(agg.x * inv_te, agg.y * inv_te,
                                        agg.z * inv_te, agg.w * inv_te));
            } else {
                float4 sv = ldg_stream4(self_v + (size_t)b * 64 + c4 * 4);
                stg_stream4(out + (size_t)b * 128 + c4 * 4, sv);
            }

            if (!has_next) break;
            b = nb;
        }
    }
}

extern "C" void kernel_launch(void* const* d_in, const int* in_sizes, int n_in,
                              void* d_out, int out_size) {
    const float* self_v = (const float*)d_in[0];
    const float* nv     = (const float*)d_in[1];
    const float* rel    = (const float*)d_in[2];
    const float* ue     = (const float*)d_in[3];
    const float* W1     = (const float*)d_in[4];
    const float* b1     = (const float*)d_in[5];
    const float* w2     = (const float*)d_in[6];
    const float* b2     = (const float*)d_in[7];
    float* out = (float*)d_out;

    cudaFuncSetAttribute(agg_kernel, cudaFuncAttributeMaxDynamicSharedMemorySize, SMEM_BYTES);
    agg_kernel<<<NCTA, 256, SMEM_BYTES>>>(self_v, nv, rel, ue, W1, b1, w2, b2, out);
}

// round 14
// speedup vs baseline: 1.0206x; 1.0206x over previous
#include <cuda_runtime.h>
#include <cstdint>

#define B_TOTAL 16384
#define RS 72                // rel row stride (floats); phase-conflict-free LDS.64
#define RELTILE (16 * RS)    // 1152 floats per m-tile buffer
#define NCTA 592             // 148 SMs x 4 resident CTAs
#define BSTRIDE (NCTA * 8)   // warp-batch stride = 4736

// ---- dynamic smem layout (float offsets), ~46.3 KB total ----
#define OFF_WPB  0           // uint2[1024]: bf16-packed B-frags of W1_lower (8 KB)
#define OFF_W2   2048        // float[64]
#define OFF_UEP  2112        // float[8][64]: per-warp uep[j]
#define OFF_REL  2624        // float[8][RELTILE]: per-warp rel buffer (36 KB)
#define SMEM_FLOATS (OFF_REL + 8 * RELTILE)
#define SMEM_BYTES  (SMEM_FLOATS * 4)

__device__ __forceinline__ void cp16(float* s, const float* g) {
    uint32_t sa = (uint32_t)__cvta_generic_to_shared(s);
    asm volatile("cp.async.cg.shared.global [%0], [%1], 16;\n" :: "r"(sa), "l"(g));
}
template <int N>
__device__ __forceinline__ void cp_wait() { asm volatile("cp.async.wait_group %0;\n" :: "n"(N)); }

// pack two f32 -> bf16x2 (lo = first arg)
__device__ __forceinline__ uint32_t pack_bf16(float lo, float hi) {
    uint32_t r;
    asm("cvt.rn.bf16x2.f32 %0, %1, %2;" : "=r"(r) : "f"(hi), "f"(lo));
    return r;
}

__device__ __forceinline__ float4 ldg_stream4(const float* g) {
    float4 v;
    asm volatile("ld.global.nc.L1::no_allocate.v4.f32 {%0,%1,%2,%3}, [%4];\n"
                 : "=f"(v.x), "=f"(v.y), "=f"(v.z), "=f"(v.w) : "l"(g));
    return v;
}
__device__ __forceinline__ void stg_stream4(float* g, float4 v) {
    asm volatile("st.global.cs.v4.f32 [%0], {%1,%2,%3,%4};\n"
                 :: "l"(g), "f"(v.x), "f"(v.y), "f"(v.z), "f"(v.w) : "memory");
}

// stage one 16x64 rel m-tile -> buf (row stride RS), per-warp, coalesced 16B chunks
__device__ __forceinline__ void stage_tile(float* buf, const float* __restrict__ src, int lane) {
#pragma unroll
    for (int c = 0; c < 8; c++) {
        int i = lane + c * 32;          // chunk 0..255
        int r = i >> 4, s4 = i & 15;
        cp16(buf + r * RS + s4 * 4, src + r * 64 + s4 * 4);
    }
    asm volatile("cp.async.commit_group;\n");
}

__global__ __launch_bounds__(256, 4) void agg_kernel(
    const float* __restrict__ self_v,
    const float* __restrict__ nv,
    const float* __restrict__ rel,
    const float* __restrict__ ue,
    const float* __restrict__ W1,
    const float* __restrict__ b1,
    const float* __restrict__ w2,
    const float* __restrict__ b2,
    float* __restrict__ out)
{
    extern __shared__ __align__(16) float smem[];
    uint2* sWpB = reinterpret_cast<uint2*>(smem + OFF_WPB);
    float* sW2  = smem + OFF_W2;

    const int tid  = threadIdx.x;
    const int warp = tid >> 5;
    const int lane = tid & 31;
    const int g = lane >> 2;          // groupID
    const int q = lane & 3;           // threadID_in_group

    float* myU = smem + OFF_UEP + warp * 64;   // uep[j]
    float* buf = smem + OFF_REL + warp * RELTILE;

    // ---- one-time W staging: bf16 B-frags for m16n8k16 (once per persistent CTA) ----
    // sWpB[(jt*4+kst)*32 + lane] = { pack(W[k0+2q][j], W[k0+2q+1][j]),
    //                               pack(W[k0+2q+8][j], W[k0+2q+9][j]) },  k0 = 16*kst, j = 8*jt+g
    for (int i = tid; i < 1024; i += 256) {
        int l2 = i & 31, jtk = i >> 5;
        int gg = l2 >> 2, qq = l2 & 3;
        int jt = jtk >> 2, kst = jtk & 3;
        int col = 8 * jt + gg;
        int row = 64 + 16 * kst + 2 * qq;
        float x0 = __ldg(W1 + (row)     * 64 + col);
        float x1 = __ldg(W1 + (row + 1) * 64 + col);
        float x2 = __ldg(W1 + (row + 8) * 64 + col);
        float x3 = __ldg(W1 + (row + 9) * 64 + col);
        sWpB[i] = make_uint2(pack_bf16(x0, x1), pack_bf16(x2, x3));
    }
    if (tid < 64) sW2[tid] = __ldg(w2 + tid);
    __syncthreads();

    const float b2v = __ldg(b2);
    const int c4 = lane & 15, half = lane >> 4;

    int b = blockIdx.x * 8 + warp;
    if (b < B_TOTAL) {
        // prologue: prefetch first batch's m-tile 0
        stage_tile(buf, rel + (size_t)b * 4096, lane);

        for (;;) {
            const float* relb = rel + (size_t)b * 4096;
            const float* nvb  = nv  + (size_t)b * 4096;
            const int nb = b + BSTRIDE;
            const bool has_next = nb < B_TOTAL;

            // ---- uep[j] = b1[j] + ue[b] @ W1_upper[:,j] (fp32; overlaps cp.async) ----
            {
                const float* ub = ue + (size_t)b * 64;
                float uev0 = __ldg(ub + lane);
                float uev1 = __ldg(ub + lane + 32);
                float acc0 = __ldg(b1 + lane);
                float acc1 = __ldg(b1 + lane + 32);
#pragma unroll
                for (int k = 0; k < 64; k++) {
                    float uk = __shfl_sync(0xffffffffu, (k < 32) ? uev0 : uev1, k & 31);
                    acc0 = fmaf(uk, __ldg(W1 + k * 64 + lane),      acc0);
                    acc1 = fmaf(uk, __ldg(W1 + k * 64 + lane + 32), acc1);
                }
                myU[lane]      = acc0;
                myU[lane + 32] = acc1;
            }

            float4 agg = make_float4(0.f, 0.f, 0.f, 0.f);
            float teAcc = 0.f;

            // ---- 4 m-tiles of 16 neighbors; bf16 MMA + fused aggregation ----
#pragma unroll
            for (int mt = 0; mt < 4; mt++) {
                cp_wait<0>();
                __syncwarp();

                // A-frags: LDS.64 fp32 pairs -> bf16x2 (phase-conflict-free, RS=72)
                uint32_t a[4][4];
#pragma unroll
                for (int kst = 0; kst < 4; kst++) {
                    const float* r0 = buf + g * RS + 16 * kst;
                    const float* r1 = r0 + 8 * RS;
                    float2 p0 = *reinterpret_cast<const float2*>(r0 + 2 * q);
                    float2 p1 = *reinterpret_cast<const float2*>(r1 + 2 * q);
                    float2 p2 = *reinterpret_cast<const float2*>(r0 + 2 * q + 8);
                    float2 p3 = *reinterpret_cast<const float2*>(r1 + 2 * q + 8);
                    a[kst][0] = pack_bf16(p0.x, p0.y);
                    a[kst][1] = pack_bf16(p1.x, p1.y);
                    a[kst][2] = pack_bf16(p2.x, p2.y);
                    a[kst][3] = pack_bf16(p3.x, p3.y);
                }

                // restage: next tile, or next batch's tile 0 (pipeline never drains)
                if (mt < 3)           stage_tile(buf, relb + (mt + 1) * 1024, lane);
                else if (has_next)    stage_tile(buf, rel + (size_t)nb * 4096, lane);

                float s0 = 0.f, s1 = 0.f;   // scores for neighbors mt*16+g, +8
#pragma unroll
                for (int jt = 0; jt < 8; jt++) {
                    float c0 = 0.f, c1 = 0.f, c2 = 0.f, c3 = 0.f;
#pragma unroll
                    for (int kst = 0; kst < 4; kst++) {
                        uint2 bv = sWpB[(jt * 4 + kst) * 32 + lane];
                        asm volatile(
                            "mma.sync.aligned.m16n8k16.row.col.f32.bf16.bf16.f32 "
                            "{%0,%1,%2,%3}, {%4,%5,%6,%7}, {%8,%9}, {%0,%1,%2,%3};\n"
                            : "+f"(c0), "+f"(c1), "+f"(c2), "+f"(c3)
                            : "r"(a[kst][0]), "r"(a[kst][1]), "r"(a[kst][2]), "r"(a[kst][3]),
                              "r"(bv.x), "r"(bv.y));
                    }
                    float u0 = myU[8 * jt + 2 * q], u1 = myU[8 * jt + 2 * q + 1];
                    float v0 = sW2[8 * jt + 2 * q], v1 = sW2[8 * jt + 2 * q + 1];
                    s0 += fmaxf(c0 + u0, 0.f) * v0 + fmaxf(c1 + u1, 0.f) * v1;
                    s1 += fmaxf(c2 + u0, 0.f) * v0 + fmaxf(c3 + u1, 0.f) * v1;
                }
                s0 += __shfl_xor_sync(0xffffffffu, s0, 1);
                s0 += __shfl_xor_sync(0xffffffffu, s0, 2);
                s1 += __shfl_xor_sync(0xffffffffu, s1, 1);
                s1 += __shfl_xor_sync(0xffffffffu, s1, 2);

                float e0 = __expf(1.f / (1.f + __expf(-(s0 + b2v))));
                float e1 = __expf(1.f / (1.f + __expf(-(s1 + b2v))));
                teAcc += e0 + e1;

                // fused aggregation for this tile's 16 neighbors (streaming loads)
                const float* nvt = nvb + mt * 1024;
#pragma unroll
                for (int i = 0; i < 8; i++) {
                    int r = 2 * i + half;                    // 0..15
                    float er = (i < 4)
                        ? __shfl_sync(0xffffffffu, e0, 4 * r)
                        : __shfl_sync(0xffffffffu, e1, 4 * (r - 8));
                    float4 v = ldg_stream4(nvt + r * 64 + c4 * 4);
                    agg.x = fmaf(er, v.x, agg.x);
                    agg.y = fmaf(er, v.y, agg.y);
                    agg.z = fmaf(er, v.z, agg.z);
                    agg.w = fmaf(er, v.w, agg.w);
                }
            }

            // softmax denominator (teAcc identical across q-lanes; sum over g)
            teAcc += __shfl_xor_sync(0xffffffffu, teAcc, 4);
            teAcc += __shfl_xor_sync(0xffffffffu, teAcc, 8);
            teAcc += __shfl_xor_sync(0xffffffffu, teAcc, 16);
            float inv_te = __fdividef(1.f, teAcc);

            agg.x += __shfl_xor_sync(0xffffffffu, agg.x, 16);
            agg.y += __shfl_xor_sync(0xffffffffu, agg.y, 16);
            agg.z += __shfl_xor_sync(0xffffffffu, agg.z, 16);
            agg.w += __shfl_xor_sync(0xffffffffu, agg.w, 16);

            if (lane < 16) {
                stg_stream4(out + (size_t)b * 128 + 64 + c4 * 4,
                            make_float4(agg.x * inv_te, agg.y * inv_te,
                                        agg.z * inv_te, agg.w * inv_te));
            } else {
                float4 sv = ldg_stream4(self_v + (size_t)b * 64 + c4 * 4);
                stg_stream4(out + (size_t)b * 128 + c4 * 4, sv);
            }

            if (!has_next) break;
            b = nb;
        }
    }
}

extern "C" void kernel_launch(void* const* d_in, const int* in_sizes, int n_in,
                              void* d_out, int out_size) {
    const float* self_v = (const float*)d_in[0];
    const float* nv     = (const float*)d_in[1];
    const float* rel    = (const float*)d_in[2];
    const float* ue     = (const float*)d_in[3];
    const float* W1     = (const float*)d_in[4];
    const float* b1     = (const float*)d_in[5];
    const float* w2     = (const float*)d_in[6];
    const float* b2     = (const float*)d_in[7];
    float* out = (float*)d_out;

    cudaFuncSetAttribute(agg_kernel, cudaFuncAttributeMaxDynamicSharedMemorySize, SMEM_BYTES);
    agg_kernel<<<NCTA, 256, SMEM_BYTES>>>(self_v, nv, rel, ue, W1, b1, w2, b2, out);
}

// round 15
// speedup vs baseline: 1.1002x; 1.0780x over previous
#include <cuda_runtime.h>
#include <cstdint>

#define B_TOTAL 16384
#define RS 72                // rel row stride (floats); phase-conflict-free LDS.64
#define RELTILE (16 * RS)    // 1152 floats per m-tile buffer
#define NCTA 444             // 148 SMs x 3 resident CTAs
#define BSTRIDE (NCTA * 8)   // warp-batch stride = 3552

// ---- dynamic smem layout (float offsets), ~46.3 KB total ----
#define OFF_WPB  0           // uint2[1024]: bf16-packed B-frags of W1_lower (8 KB)
#define OFF_W2   2048        // float[64]
#define OFF_UEP  2112        // float[8][64]: per-warp uep[j]
#define OFF_REL  2624        // float[8][RELTILE]: per-warp rel buffer (36 KB)
#define SMEM_FLOATS (OFF_REL + 8 * RELTILE)
#define SMEM_BYTES  (SMEM_FLOATS * 4)

__device__ __forceinline__ void cp16(float* s, const float* g) {
    uint32_t sa = (uint32_t)__cvta_generic_to_shared(s);
    asm volatile("cp.async.cg.shared.global [%0], [%1], 16;\n" :: "r"(sa), "l"(g));
}
template <int N>
__device__ __forceinline__ void cp_wait() { asm volatile("cp.async.wait_group %0;\n" :: "n"(N)); }

// pack two f32 -> bf16x2 (lo = first arg)
__device__ __forceinline__ uint32_t pack_bf16(float lo, float hi) {
    uint32_t r;
    asm("cvt.rn.bf16x2.f32 %0, %1, %2;" : "=r"(r) : "f"(hi), "f"(lo));
    return r;
}

__device__ __forceinline__ float4 ldg_stream4(const float* g) {
    float4 v;
    asm volatile("ld.global.nc.L1::no_allocate.v4.f32 {%0,%1,%2,%3}, [%4];\n"
                 : "=f"(v.x), "=f"(v.y), "=f"(v.z), "=f"(v.w) : "l"(g));
    return v;
}
__device__ __forceinline__ void stg_stream4(float* g, float4 v) {
    asm volatile("st.global.cs.v4.f32 [%0], {%1,%2,%3,%4};\n"
                 :: "l"(g), "f"(v.x), "f"(v.y), "f"(v.z), "f"(v.w) : "memory");
}

// stage one 16x64 rel m-tile -> buf (row stride RS), per-warp, coalesced 16B chunks
__device__ __forceinline__ void stage_tile(float* buf, const float* __restrict__ src, int lane) {
#pragma unroll
    for (int c = 0; c < 8; c++) {
        int i = lane + c * 32;          // chunk 0..255
        int r = i >> 4, s4 = i & 15;
        cp16(buf + r * RS + s4 * 4, src + r * 64 + s4 * 4);
    }
    asm volatile("cp.async.commit_group;\n");
}

__global__ __launch_bounds__(256, 3) void agg_kernel(
    const float* __restrict__ self_v,
    const float* __restrict__ nv,
    const float* __restrict__ rel,
    const float* __restrict__ ue,
    const float* __restrict__ W1,
    const float* __restrict__ b1,
    const float* __restrict__ w2,
    const float* __restrict__ b2,
    float* __restrict__ out)
{
    extern __shared__ __align__(16) float smem[];
    uint2* sWpB = reinterpret_cast<uint2*>(smem + OFF_WPB);
    float* sW2  = smem + OFF_W2;

    const int tid  = threadIdx.x;
    const int warp = tid >> 5;
    const int lane = tid & 31;
    const int g = lane >> 2;          // groupID
    const int q = lane & 3;           // threadID_in_group

    float* myU = smem + OFF_UEP + warp * 64;   // uep[j]
    float* buf = smem + OFF_REL + warp * RELTILE;

    // ---- one-time W staging: bf16 B-frags for m16n8k16 (once per persistent CTA) ----
    for (int i = tid; i < 1024; i += 256) {
        int l2 = i & 31, jtk = i >> 5;
        int gg = l2 >> 2, qq = l2 & 3;
        int jt = jtk >> 2, kst = jtk & 3;
        int col = 8 * jt + gg;
        int row = 64 + 16 * kst + 2 * qq;
        float x0 = __ldg(W1 + (row)     * 64 + col);
        float x1 = __ldg(W1 + (row + 1) * 64 + col);
        float x2 = __ldg(W1 + (row + 8) * 64 + col);
        float x3 = __ldg(W1 + (row + 9) * 64 + col);
        sWpB[i] = make_uint2(pack_bf16(x0, x1), pack_bf16(x2, x3));
    }
    if (tid < 64) sW2[tid] = __ldg(w2 + tid);
    __syncthreads();

    const float b2v = __ldg(b2);
    const int c4 = lane & 15, half = lane >> 4;

    int b = blockIdx.x * 8 + warp;
    if (b < B_TOTAL) {
        // prologue: prefetch first batch's m-tile 0
        stage_tile(buf, rel + (size_t)b * 4096, lane);

        for (;;) {
            const float* relb = rel + (size_t)b * 4096;
            const float* nvb  = nv  + (size_t)b * 4096;
            const int nb = b + BSTRIDE;
            const bool has_next = nb < B_TOTAL;

            // ---- uep[j] = b1[j] + ue[b] @ W1_upper[:,j] (fp32; overlaps cp.async) ----
            {
                const float* ub = ue + (size_t)b * 64;
                float uev0 = __ldg(ub + lane);
                float uev1 = __ldg(ub + lane + 32);
                float acc0 = __ldg(b1 + lane);
                float acc1 = __ldg(b1 + lane + 32);
#pragma unroll
                for (int k = 0; k < 64; k++) {
                    float uk = __shfl_sync(0xffffffffu, (k < 32) ? uev0 : uev1, k & 31);
                    acc0 = fmaf(uk, __ldg(W1 + k * 64 + lane),      acc0);
                    acc1 = fmaf(uk, __ldg(W1 + k * 64 + lane + 32), acc1);
                }
                myU[lane]      = acc0;
                myU[lane + 32] = acc1;
            }

            float4 agg = make_float4(0.f, 0.f, 0.f, 0.f);
            float teAcc = 0.f;

            // ---- 4 m-tiles of 16 neighbors; bf16 MMA + fused aggregation ----
#pragma unroll
            for (int mt = 0; mt < 4; mt++) {
                cp_wait<0>();
                __syncwarp();

                // A-frags: LDS.64 fp32 pairs -> bf16x2 (phase-conflict-free, RS=72)
                uint32_t a[4][4];
#pragma unroll
                for (int kst = 0; kst < 4; kst++) {
                    const float* r0 = buf + g * RS + 16 * kst;
                    const float* r1 = r0 + 8 * RS;
                    float2 p0 = *reinterpret_cast<const float2*>(r0 + 2 * q);
                    float2 p1 = *reinterpret_cast<const float2*>(r1 + 2 * q);
                    float2 p2 = *reinterpret_cast<const float2*>(r0 + 2 * q + 8);
                    float2 p3 = *reinterpret_cast<const float2*>(r1 + 2 * q + 8);
                    a[kst][0] = pack_bf16(p0.x, p0.y);
                    a[kst][1] = pack_bf16(p1.x, p1.y);
                    a[kst][2] = pack_bf16(p2.x, p2.y);
                    a[kst][3] = pack_bf16(p3.x, p3.y);
                }

                // restage: next tile, or next batch's tile 0 (pipeline never drains)
                if (mt < 3)           stage_tile(buf, relb + (mt + 1) * 1024, lane);
                else if (has_next)    stage_tile(buf, rel + (size_t)nb * 4096, lane);

                float s0 = 0.f, s1 = 0.f;   // scores for neighbors mt*16+g, +8
#pragma unroll
                for (int jt = 0; jt < 8; jt++) {
                    float c0 = 0.f, c1 = 0.f, c2 = 0.f, c3 = 0.f;
#pragma unroll
                    for (int kst = 0; kst < 4; kst++) {
                        uint2 bv = sWpB[(jt * 4 + kst) * 32 + lane];
                        asm volatile(
                            "mma.sync.aligned.m16n8k16.row.col.f32.bf16.bf16.f32 "
                            "{%0,%1,%2,%3}, {%4,%5,%6,%7}, {%8,%9}, {%0,%1,%2,%3};\n"
                            : "+f"(c0), "+f"(c1), "+f"(c2), "+f"(c3)
                            : "r"(a[kst][0]), "r"(a[kst][1]), "r"(a[kst][2]), "r"(a[kst][3]),
                              "r"(bv.x), "r"(bv.y));
                    }
                    float u0 = myU[8 * jt + 2 * q], u1 = myU[8 * jt + 2 * q + 1];
                    float v0 = sW2[8 * jt + 2 * q], v1 = sW2[8 * jt + 2 * q + 1];
                    s0 += fmaxf(c0 + u0, 0.f) * v0 + fmaxf(c1 + u1, 0.f) * v1;
                    s1 += fmaxf(c2 + u0, 0.f) * v0 + fmaxf(c3 + u1, 0.f) * v1;
                }

                // ---- hoisted nv group A (rows 2i+half, i=0..3): latency hides
                // behind the shfl/sigmoid/exp chain below (A-array now dead) ----
                const float* nvt = nvb + mt * 1024;
                float4 va0 = ldg_stream4(nvt + (0 + half) * 64 + c4 * 4);
                float4 va1 = ldg_stream4(nvt + (2 + half) * 64 + c4 * 4);
                float4 va2 = ldg_stream4(nvt + (4 + half) * 64 + c4 * 4);
                float4 va3 = ldg_stream4(nvt + (6 + half) * 64 + c4 * 4);

                s0 += __shfl_xor_sync(0xffffffffu, s0, 1);
                s0 += __shfl_xor_sync(0xffffffffu, s0, 2);
                s1 += __shfl_xor_sync(0xffffffffu, s1, 1);
                s1 += __shfl_xor_sync(0xffffffffu, s1, 2);

                float e0 = __expf(1.f / (1.f + __expf(-(s0 + b2v))));
                float e1 = __expf(1.f / (1.f + __expf(-(s1 + b2v))));
                teAcc += e0 + e1;

                // group B loads (rows 8+2i+half); covered by group-A FMAs + shfls
                float4 vb0 = ldg_stream4(nvt + (8  + half) * 64 + c4 * 4);
                float4 vb1 = ldg_stream4(nvt + (10 + half) * 64 + c4 * 4);
                float4 vb2 = ldg_stream4(nvt + (12 + half) * 64 + c4 * 4);
                float4 vb3 = ldg_stream4(nvt + (14 + half) * 64 + c4 * 4);

                // group A FMAs (weights e0 for rows 0..7)
                {
                    float w0 = __shfl_sync(0xffffffffu, e0, 4 * (0 + half));
                    float w1 = __shfl_sync(0xffffffffu, e0, 4 * (2 + half));
                    float w2s = __shfl_sync(0xffffffffu, e0, 4 * (4 + half));
                    float w3 = __shfl_sync(0xffffffffu, e0, 4 * (6 + half));
                    agg.x = fmaf(w0, va0.x, agg.x); agg.y = fmaf(w0, va0.y, agg.y);
                    agg.z = fmaf(w0, va0.z, agg.z); agg.w = fmaf(w0, va0.w, agg.w);
                    agg.x = fmaf(w1, va1.x, agg.x); agg.y = fmaf(w1, va1.y, agg.y);
                    agg.z = fmaf(w1, va1.z, agg.z); agg.w = fmaf(w1, va1.w, agg.w);
                    agg.x = fmaf(w2s, va2.x, agg.x); agg.y = fmaf(w2s, va2.y, agg.y);
                    agg.z = fmaf(w2s, va2.z, agg.z); agg.w = fmaf(w2s, va2.w, agg.w);
                    agg.x = fmaf(w3, va3.x, agg.x); agg.y = fmaf(w3, va3.y, agg.y);
                    agg.z = fmaf(w3, va3.z, agg.z); agg.w = fmaf(w3, va3.w, agg.w);
                }
                // group B FMAs (weights e1 for rows 8..15; row index within e1 = r-8)
                {
                    float w0 = __shfl_sync(0xffffffffu, e1, 4 * (0 + half));
                    float w1 = __shfl_sync(0xffffffffu, e1, 4 * (2 + half));
                    float w2s = __shfl_sync(0xffffffffu, e1, 4 * (4 + half));
                    float w3 = __shfl_sync(0xffffffffu, e1, 4 * (6 + half));
                    agg.x = fmaf(w0, vb0.x, agg.x); agg.y = fmaf(w0, vb0.y, agg.y);
                    agg.z = fmaf(w0, vb0.z, agg.z); agg.w = fmaf(w0, vb0.w, agg.w);
                    agg.x = fmaf(w1, vb1.x, agg.x); agg.y = fmaf(w1, vb1.y, agg.y);
                    agg.z = fmaf(w1, vb1.z, agg.z); agg.w = fmaf(w1, vb1.w, agg.w);
                    agg.x = fmaf(w2s, vb2.x, agg.x); agg.y = fmaf(w2s, vb2.y, agg.y);
                    agg.z = fmaf(w2s, vb2.z, agg.z); agg.w = fmaf(w2s, vb2.w, agg.w);
                    agg.x = fmaf(w3, vb3.x, agg.x); agg.y = fmaf(w3, vb3.y, agg.y);
                    agg.z = fmaf(w3, vb3.z, agg.z); agg.w = fmaf(w3, vb3.w, agg.w);
                }
            }

            // softmax denominator (teAcc identical across q-lanes; sum over g)
            teAcc += __shfl_xor_sync(0xffffffffu, teAcc, 4);
            teAcc += __shfl_xor_sync(0xffffffffu, teAcc, 8);
            teAcc += __shfl_xor_sync(0xffffffffu, teAcc, 16);
            float inv_te = __fdividef(1.f, teAcc);

            agg.x += __shfl_xor_sync(0xffffffffu, agg.x, 16);
            agg.y += __shfl_xor_sync(0xffffffffu, agg.y, 16);
            agg.z += __shfl_xor_sync(0xffffffffu, agg.z, 16);
            agg.w += __shfl_xor_sync(0xffffffffu, agg.w, 16);

            if (lane < 16) {
                stg_stream4(out + (size_t)b * 128 + 64 + c4 * 4,
                            make_float4(agg.x * inv_te, agg.y * inv_te,
                                        agg.z * inv_te, agg.w * inv_te));
            } else {
                float4 sv = ldg_stream4(self_v + (size_t)b * 64 + c4 * 4);
                stg_stream4(out + (size_t)b * 128 + c4 * 4, sv);
            }

            if (!has_next) break;
            b = nb;
        }
    }
}

extern "C" void kernel_launch(void* const* d_in, const int* in_sizes, int n_in,
                              void* d_out, int out_size) {
    const float* self_v = (const float*)d_in[0];
    const float* nv     = (const float*)d_in[1];
    const float* rel    = (const float*)d_in[2];
    const float* ue     = (const float*)d_in[3];
    const float* W1     = (const float*)d_in[4];
    const float* b1     = (const float*)d_in[5];
    const float* w2     = (const float*)d_in[6];
    const float* b2     = (const float*)d_in[7];
    float* out = (float*)d_out;

    cudaFuncSetAttribute(agg_kernel, cudaFuncAttributeMaxDynamicSharedMemorySize, SMEM_BYTES);
    agg_kernel<<<NCTA, 256, SMEM_BYTES>>>(self_v, nv, rel, ue, W1, b1, w2, b2, out);
}